// round 4
// baseline (speedup 1.0000x reference)
#include <cuda_runtime.h>

#define NN 100000
#define EE 1000000
#define ENE (EE + NN)          // edges + self loops
#define EN12 (ENE * 12)

// ---------------- static device scratch (no allocations allowed) ----------------
__device__ __align__(16) int   g_src[EE];
__device__ __align__(16) int   g_dst[EE];
__device__ __align__(16) int   g_cnt[NN];
__device__ __align__(16) int   g_rowstart[NN + 1];
__device__ __align__(16) int   g_cursor[NN];
__device__ __align__(16) int   g_csr_eid[EE];
__device__ __align__(16) int   g_csr_src[EE];
__device__ __align__(16) float g_dinv[NN];
__device__ __align__(16) int   g_blocksum[128];

__device__ __align__(16) float g_h[NN * 64];          // SSG pre-GEMM
__device__ __align__(16) float g_x1[NN * 64];         // SSG output
__device__ __align__(16) float g_xl1[NN * 144];
__device__ __align__(16) float g_xr1[NN * 144];
__device__ __align__(16) float g_w1[ENE * 12];        // exp(logit) per (edge, head)
__device__ __align__(16) float g_den1[NN * 12];
__device__ __align__(16) float g_x2[NN * 144];        // GAT1 output
__device__ __align__(16) float g_xl2[NN * 64];
__device__ __align__(16) float g_xr2[NN * 64];
__device__ __align__(16) float g_w2[ENE];
__device__ __align__(16) float g_den2[NN];

__device__ __forceinline__ float lrelu(float v) { return v > 0.f ? v : 0.2f * v; }

// ---------------- init: zero counters / denominators ----------------
__global__ void k_init() {
    int i = blockIdx.x * blockDim.x + threadIdx.x;
    if (i < NN) { g_cnt[i] = 0; g_den2[i] = 0.f; }
    if (i < NN * 12) g_den1[i] = 0.f;
}

// ---------------- edge convert + in-degree count ----------------
// edge_index is INT32 (JAX x64 disabled: astype(int64) is a silent no-op).
__global__ void k_count(const int* __restrict__ ei) {
    int e = blockIdx.x * blockDim.x + threadIdx.x;
    if (e >= EE) return;
    int s = ei[e];
    int d = ei[EE + e];
    g_src[e] = s;
    g_dst[e] = d;
    atomicAdd(&g_cnt[d], 1);
}

// ---------------- 3-kernel exclusive scan over g_cnt -> g_rowstart ----------------
__global__ void k_scan1() {   // grid 98, block 1024
    __shared__ int sm[1024];
    int i = blockIdx.x * 1024 + threadIdx.x;
    int v = (i < NN) ? g_cnt[i] : 0;
    if (i < NN) g_dinv[i] = rsqrtf((float)(v + 1));   // deg incl. self loop
    sm[threadIdx.x] = v;
    __syncthreads();
    for (int off = 1; off < 1024; off <<= 1) {
        int t = 0;
        if (threadIdx.x >= off) t = sm[threadIdx.x - off];
        __syncthreads();
        sm[threadIdx.x] += t;
        __syncthreads();
    }
    if (i < NN) g_rowstart[i] = sm[threadIdx.x] - v;   // block-local exclusive
    if (threadIdx.x == 1023) g_blocksum[blockIdx.x] = sm[1023];
}
__global__ void k_scan2(int nb) {  // 1 block
    if (threadIdx.x == 0) {
        int acc = 0;
        for (int b = 0; b < nb; b++) { int t = g_blocksum[b]; g_blocksum[b] = acc; acc += t; }
    }
}
__global__ void k_scan3() {
    int i = blockIdx.x * 1024 + threadIdx.x;
    if (i < NN) {
        int v = g_rowstart[i] + g_blocksum[blockIdx.x];
        g_rowstart[i] = v;
        g_cursor[i]   = v;
    }
    if (i == 0) g_rowstart[NN] = EE;
}

// ---------------- scatter edges into CSR (dst-grouped) ----------------
__global__ void k_scatter() {
    int e = blockIdx.x * blockDim.x + threadIdx.x;
    if (e >= EE) return;
    int d = g_dst[e];
    int pos = atomicAdd(&g_cursor[d], 1);
    g_csr_eid[pos] = e;
    g_csr_src[pos] = g_src[e];
}

// ---------------- SSGConv aggregation: h = a*x + (1-a)*agg ----------------
__global__ void k_ssg(const float* __restrict__ x) {
    int d = blockIdx.x, c = threadIdx.x;
    float dd  = g_dinv[d];
    float xc  = x[d * 64 + c];
    float acc = xc * dd * dd;      // self loop
    int beg = g_rowstart[d], end = g_rowstart[d + 1];
    for (int i = beg; i < end; i++) {
        int s = g_csr_src[i];
        acc += x[s * 64 + c] * g_dinv[s] * dd;
    }
    g_h[d * 64 + c] = 0.5f * xc + 0.5f * acc;
}

// ---------------- skinny GEMM: Y[N,M] = X[N,K] @ W[K,M] + b ----------------
// SEL chooses src/dst from the __device__ globals at compile time.
template <int SEL, int K, int M, int CPT>
__global__ void gemm_bias(const float* __restrict__ W, const float* __restrict__ b) {
    const float* X;
    float* Y;
    if constexpr (SEL == 0)      { X = g_h;  Y = g_x1;  }
    else if constexpr (SEL == 1) { X = g_x1; Y = g_xl1; }
    else if constexpr (SEL == 2) { X = g_x1; Y = g_xr1; }
    else if constexpr (SEL == 3) { X = g_x2; Y = g_xl2; }
    else                         { X = g_x2; Y = g_xr2; }

    constexpr int ROWS = 16, RPT = 4;
    constexpr int TC = M / CPT, TR = ROWS / RPT, NT = TC * TR;
    constexpr int KS = K + 1;
    __shared__ float Ws[K * M];
    __shared__ float Xs[ROWS * KS];
    int row0 = blockIdx.x * ROWS;
    for (int i = threadIdx.x; i < K * M; i += NT) Ws[i] = W[i];
    for (int i = threadIdx.x; i < ROWS * K; i += NT) {
        int r = i / K, k = i - r * K;
        Xs[r * KS + k] = X[(row0 + r) * K + k];
    }
    __syncthreads();
    int tc = threadIdx.x % TC;
    int tr = threadIdx.x / TC;
    float acc[RPT][CPT];
    #pragma unroll
    for (int rr = 0; rr < RPT; rr++)
        #pragma unroll
        for (int cc = 0; cc < CPT; cc++) acc[rr][cc] = b[tc + cc * TC];
    #pragma unroll 4
    for (int k = 0; k < K; k++) {
        float xv[RPT], wv[CPT];
        #pragma unroll
        for (int rr = 0; rr < RPT; rr++) xv[rr] = Xs[(tr * RPT + rr) * KS + k];
        #pragma unroll
        for (int cc = 0; cc < CPT; cc++) wv[cc] = Ws[k * M + tc + cc * TC];
        #pragma unroll
        for (int rr = 0; rr < RPT; rr++)
            #pragma unroll
            for (int cc = 0; cc < CPT; cc++) acc[rr][cc] += xv[rr] * wv[cc];
    }
    #pragma unroll
    for (int rr = 0; rr < RPT; rr++) {
        int r = row0 + tr * RPT + rr;
        #pragma unroll
        for (int cc = 0; cc < CPT; cc++) Y[r * M + tc + cc * TC] = acc[rr][cc];
    }
}

// ---------------- GAT1: logits -> w = exp(logit), accumulate denominator ----------------
// Softmax is shift-invariant; logits here are O(1) by construction, so no max
// subtraction is needed (exp stays far from overflow/underflow).
__global__ void k_logits1(const float* __restrict__ att) {
    __shared__ float atts[144];
    for (int i = threadIdx.x; i < 144; i += blockDim.x) atts[i] = att[i];
    __syncthreads();
    int i = blockIdx.x * blockDim.x + threadIdx.x;
    if (i >= EN12) return;
    int e = i / 12, h = i - e * 12;
    int s, d;
    if (e < EE) { s = g_src[e]; d = g_dst[e]; } else { s = e - EE; d = s; }
    const float* xl = g_xl1 + s * 144 + h * 12;
    const float* xr = g_xr1 + d * 144 + h * 12;
    float acc = 0.f;
    #pragma unroll
    for (int j = 0; j < 12; j++) acc += lrelu(xl[j] + xr[j]) * atts[h * 12 + j];
    float w = __expf(acc);
    g_w1[i] = w;
    atomicAdd(&g_den1[d * 12 + h], w);
}

// ---------------- GAT1 aggregation (CSR, one block per dst, 144 threads) ----------------
__global__ void k_agg1(const float* __restrict__ bias) {
    int d = blockIdx.x, c = threadIdx.x;
    int h = c / 12;
    float acc = g_w1[(EE + d) * 12 + h] * g_xl1[d * 144 + c];   // self loop
    int beg = g_rowstart[d], end = g_rowstart[d + 1];
    for (int i = beg; i < end; i++) {
        int eid = g_csr_eid[i];
        int s   = g_csr_src[i];
        acc += g_w1[eid * 12 + h] * g_xl1[s * 144 + c];
    }
    g_x2[d * 144 + c] = acc / (g_den1[d * 12 + h] + 1e-16f) + bias[c];
}

// ---------------- GAT2 logits: one warp per edge ----------------
__global__ void k_logits2(const float* __restrict__ att) {
    int t = blockIdx.x * blockDim.x + threadIdx.x;
    int e = t >> 5, lane = t & 31;
    if (e >= ENE) return;
    int s, d;
    if (e < EE) { s = g_src[e]; d = g_dst[e]; } else { s = e - EE; d = s; }
    float acc = 0.f;
    #pragma unroll
    for (int j = 0; j < 2; j++) {
        int c = lane + j * 32;
        float v = g_xl2[s * 64 + c] + g_xr2[d * 64 + c];
        acc += lrelu(v) * att[c];
    }
    #pragma unroll
    for (int o = 16; o > 0; o >>= 1) acc += __shfl_down_sync(0xffffffffu, acc, o);
    if (lane == 0) {
        float w = __expf(acc);
        g_w2[e] = w;
        atomicAdd(&g_den2[d], w);
    }
}

// ---------------- GAT2 aggregation -> output ----------------
__global__ void k_agg2(const float* __restrict__ bias, float* __restrict__ out) {
    int d = blockIdx.x, c = threadIdx.x;
    float acc = g_w2[EE + d] * g_xl2[d * 64 + c];
    int beg = g_rowstart[d], end = g_rowstart[d + 1];
    for (int i = beg; i < end; i++) {
        acc += g_w2[g_csr_eid[i]] * g_xl2[g_csr_src[i] * 64 + c];
    }
    out[d * 64 + c] = acc / (g_den2[d] + 1e-16f) + bias[c];
}

// ---------------- launch ----------------
extern "C" void kernel_launch(void* const* d_in, const int* in_sizes, int n_in,
                              void* d_out, int out_size) {
    const float* features = (const float*)d_in[0];
    const int*   edge_idx = (const int*)d_in[1];     // int32! (JAX default)
    const float* W_ssg = (const float*)d_in[2];
    const float* b_ssg = (const float*)d_in[3];
    const float* W1l   = (const float*)d_in[4];
    const float* b1l   = (const float*)d_in[5];
    const float* W1r   = (const float*)d_in[6];
    const float* b1r   = (const float*)d_in[7];
    const float* att1  = (const float*)d_in[8];
    const float* bias1 = (const float*)d_in[9];
    const float* W2l   = (const float*)d_in[10];
    const float* b2l   = (const float*)d_in[11];
    const float* W2r   = (const float*)d_in[12];
    const float* b2r   = (const float*)d_in[13];
    const float* att2  = (const float*)d_in[14];
    const float* bias2 = (const float*)d_in[15];
    float* out = (float*)d_out;

    const int NB = (NN + 1023) / 1024;   // 98

    // CSR build
    k_init<<<(NN * 12 + 255) / 256, 256>>>();
    k_count<<<(EE + 255) / 256, 256>>>(edge_idx);
    k_scan1<<<NB, 1024>>>();
    k_scan2<<<1, 32>>>(NB);
    k_scan3<<<NB, 1024>>>();
    k_scatter<<<(EE + 255) / 256, 256>>>();

    // SSGConv
    k_ssg<<<NN, 64>>>(features);
    gemm_bias<0, 64, 64, 2><<<NN / 16, 128>>>(W_ssg, b_ssg);

    // GATv2 layer 1 (12 heads x 12)
    gemm_bias<1, 64, 144, 4><<<NN / 16, 144>>>(W1l, b1l);
    gemm_bias<2, 64, 144, 4><<<NN / 16, 144>>>(W1r, b1r);
    k_logits1<<<(EN12 + 255) / 256, 256>>>(att1);
    k_agg1<<<NN, 144>>>(bias1);

    // GATv2 layer 2 (1 head x 64)
    gemm_bias<3, 144, 64, 2><<<NN / 16, 128>>>(W2l, b2l);
    gemm_bias<4, 144, 64, 2><<<NN / 16, 128>>>(W2r, b2r);
    k_logits2<<<(ENE * 32 + 255) / 256, 256>>>(att2);
    k_agg2<<<NN, 64>>>(bias2, out);
}

// round 5
// speedup vs baseline: 1.3407x; 1.3407x over previous
#include <cuda_runtime.h>

#define NN 100000
#define EE 1000000

// ---------------- static device scratch ----------------
__device__ __align__(16) int   g_dst[EE];
__device__ __align__(16) int   g_srcbuf[EE];
__device__ __align__(16) int   g_cnt[NN];
__device__ __align__(16) int   g_rowstart[NN + 1];
__device__ __align__(16) int   g_cursor[NN];
__device__ __align__(16) int   g_csr_src[EE];
__device__ __align__(16) float g_dinv[NN];
__device__ __align__(16) int   g_blocksum[128];

__device__ __align__(16) float g_h[NN * 64];
__device__ __align__(16) float g_x1[NN * 64];
__device__ __align__(16) float g_xl1[NN * 144];
__device__ __align__(16) float g_xr1[NN * 144];
__device__ __align__(16) float g_x2[NN * 144];
__device__ __align__(16) float g_xl2[NN * 64];
__device__ __align__(16) float g_xr2[NN * 64];

__device__ __forceinline__ float lrelu(float v) { return v > 0.f ? v : 0.2f * v; }

// ---------------- init ----------------
__global__ void k_init() {
    int i = blockIdx.x * blockDim.x + threadIdx.x;
    if (i < NN) g_cnt[i] = 0;
}

// ---------------- edge convert + in-degree count (edge_index is int32) ----------------
__global__ void k_count(const int* __restrict__ ei) {
    int e = blockIdx.x * blockDim.x + threadIdx.x;
    if (e >= EE) return;
    int s = ei[e];
    int d = ei[EE + e];
    g_srcbuf[e] = s;
    g_dst[e] = d;
    atomicAdd(&g_cnt[d], 1);
}

// ---------------- 3-kernel exclusive scan ----------------
__global__ void k_scan1() {
    __shared__ int sm[1024];
    int i = blockIdx.x * 1024 + threadIdx.x;
    int v = (i < NN) ? g_cnt[i] : 0;
    if (i < NN) g_dinv[i] = rsqrtf((float)(v + 1));
    sm[threadIdx.x] = v;
    __syncthreads();
    for (int off = 1; off < 1024; off <<= 1) {
        int t = 0;
        if (threadIdx.x >= off) t = sm[threadIdx.x - off];
        __syncthreads();
        sm[threadIdx.x] += t;
        __syncthreads();
    }
    if (i < NN) g_rowstart[i] = sm[threadIdx.x] - v;
    if (threadIdx.x == 1023) g_blocksum[blockIdx.x] = sm[1023];
}
__global__ void k_scan2(int nb) {
    if (threadIdx.x == 0) {
        int acc = 0;
        for (int b = 0; b < nb; b++) { int t = g_blocksum[b]; g_blocksum[b] = acc; acc += t; }
    }
}
__global__ void k_scan3() {
    int i = blockIdx.x * 1024 + threadIdx.x;
    if (i < NN) {
        int v = g_rowstart[i] + g_blocksum[blockIdx.x];
        g_rowstart[i] = v;
        g_cursor[i]   = v;
    }
    if (i == 0) g_rowstart[NN] = EE;
}

// ---------------- scatter edges into CSR (src only — no eid needed) ----------------
__global__ void k_scatter() {
    int e = blockIdx.x * blockDim.x + threadIdx.x;
    if (e >= EE) return;
    int d = g_dst[e];
    int pos = atomicAdd(&g_cursor[d], 1);
    g_csr_src[pos] = g_srcbuf[e];
}

// ---------------- SSGConv aggregation (prefetched) ----------------
__global__ void k_ssg(const float* __restrict__ x) {
    int d = blockIdx.x, c = threadIdx.x;
    float dd  = g_dinv[d];
    float xc  = x[d * 64 + c];
    float acc = xc * dd * dd;
    int beg = g_rowstart[d], end = g_rowstart[d + 1];
    int sN = 0; float xN = 0.f, dN = 0.f;
    if (beg < end) { sN = g_csr_src[beg]; xN = x[sN * 64 + c]; dN = g_dinv[sN]; }
    for (int i = beg; i < end; i++) {
        float xv = xN, dv = dN;
        if (i + 1 < end) { int s2 = g_csr_src[i + 1]; xN = x[s2 * 64 + c]; dN = g_dinv[s2]; }
        acc += xv * dv * dd;
    }
    g_h[d * 64 + c] = 0.5f * xc + 0.5f * acc;
}

// ---------------- skinny GEMM: 64 rows per block (4 chunks reuse smem W) ----------------
template <int SEL, int K, int M, int CPT>
__global__ void gemm_bias(const float* __restrict__ W, const float* __restrict__ b) {
    const float* X;
    float* Y;
    if constexpr (SEL == 0)      { X = g_h;  Y = g_x1;  }
    else if constexpr (SEL == 1) { X = g_x1; Y = g_xl1; }
    else if constexpr (SEL == 2) { X = g_x1; Y = g_xr1; }
    else if constexpr (SEL == 3) { X = g_x2; Y = g_xl2; }
    else                         { X = g_x2; Y = g_xr2; }

    constexpr int ROWS = 16, RPT = 4, CHUNK = 4;
    constexpr int TC = M / CPT, TR = ROWS / RPT, NT = TC * TR;
    constexpr int K4 = K / 4;
    __shared__ float Ws[K * M];
    __shared__ float Xs[ROWS * K];

    for (int i = threadIdx.x; i < K * M; i += NT) Ws[i] = W[i];

    int tc = threadIdx.x % TC;
    int tr = threadIdx.x / TC;
    float bv[CPT];
    #pragma unroll
    for (int cc = 0; cc < CPT; cc++) bv[cc] = b[tc + cc * TC];

    #pragma unroll
    for (int ch = 0; ch < CHUNK; ch++) {
        int row0 = (blockIdx.x * CHUNK + ch) * ROWS;
        __syncthreads();
        for (int i4 = threadIdx.x; i4 < ROWS * K4; i4 += NT) {
            int r = row0 + i4 / K4;
            int c4 = i4 % K4;
            if (r >= NN) r = NN - 1;
            float4 v = *(const float4*)&X[r * K + c4 * 4];
            *(float4*)&Xs[i4 * 4 - (i4 / K4) * K4 * 4 + (i4 / K4) * K] = v; // == Xs[(i4/K4)*K + c4*4]
        }
        __syncthreads();
        float acc[RPT][CPT];
        #pragma unroll
        for (int rr = 0; rr < RPT; rr++)
            #pragma unroll
            for (int cc = 0; cc < CPT; cc++) acc[rr][cc] = bv[cc];
        #pragma unroll 4
        for (int k = 0; k < K; k++) {
            float xv[RPT], wv[CPT];
            #pragma unroll
            for (int rr = 0; rr < RPT; rr++) xv[rr] = Xs[(tr * RPT + rr) * K + k];
            #pragma unroll
            for (int cc = 0; cc < CPT; cc++) wv[cc] = Ws[k * M + tc + cc * TC];
            #pragma unroll
            for (int rr = 0; rr < RPT; rr++)
                #pragma unroll
                for (int cc = 0; cc < CPT; cc++) acc[rr][cc] += xv[rr] * wv[cc];
        }
        #pragma unroll
        for (int rr = 0; rr < RPT; rr++) {
            int r = row0 + tr * RPT + rr;
            if (r < NN) {
                #pragma unroll
                for (int cc = 0; cc < CPT; cc++) Y[r * M + tc + cc * TC] = acc[rr][cc];
            }
        }
    }
}

// ---------------- fused GATv2 layer 1: softmax + aggregate in one pass ----------------
// One block per dst, 144 threads (channel c, head h=c/12). No max subtraction:
// logits are O(1) by construction, exp stays in safe fp32 range.
__global__ void k_gat1(const float* __restrict__ att, const float* __restrict__ bias) {
    int d = blockIdx.x, c = threadIdx.x;
    int h = c / 12;
    __shared__ float prod[144];
    __shared__ float wsh[12];
    __shared__ float dsh[12];

    float attc = __ldg(&att[c]);
    float xrc  = g_xr1[d * 144 + c];
    float xld  = g_xl1[d * 144 + c];

    int beg = g_rowstart[d], end = g_rowstart[d + 1];
    int sN = 0; float xlN = 0.f;
    if (beg < end) { sN = g_csr_src[beg]; xlN = g_xl1[sN * 144 + c]; }

    // self loop
    prod[c] = lrelu(xld + xrc) * attc;
    __syncthreads();
    float den = 0.f;
    if (c < 12) {
        float s = 0.f;
        #pragma unroll
        for (int j = 0; j < 12; j++) s += prod[c * 12 + j];
        float wv = __expf(s);
        wsh[c] = wv;
        den = wv;
    }
    __syncthreads();
    float acc = wsh[h] * xld;

    for (int i = beg; i < end; i++) {
        float xls = xlN;
        if (i + 1 < end) { int s2 = g_csr_src[i + 1]; xlN = g_xl1[s2 * 144 + c]; }
        __syncthreads();                 // wsh consumed by all before overwrite
        prod[c] = lrelu(xls + xrc) * attc;
        __syncthreads();
        if (c < 12) {
            float s = 0.f;
            #pragma unroll
            for (int j = 0; j < 12; j++) s += prod[c * 12 + j];
            float wv = __expf(s);
            wsh[c] = wv;
            den += wv;
        }
        __syncthreads();
        acc += wsh[h] * xls;
    }
    if (c < 12) dsh[c] = den;
    __syncthreads();
    g_x2[d * 144 + c] = acc / (dsh[h] + 1e-16f) + bias[c];
}

// ---------------- fused GATv2 layer 2 (1 head x 64) ----------------
__global__ void k_gat2(const float* __restrict__ att, const float* __restrict__ bias,
                       float* __restrict__ out) {
    int d = blockIdx.x, c = threadIdx.x;   // 64 threads
    __shared__ float part[2];

    float attc = __ldg(&att[c]);
    float xrc  = g_xr2[d * 64 + c];
    float xld  = g_xl2[d * 64 + c];

    int beg = g_rowstart[d], end = g_rowstart[d + 1];
    int sN = 0; float xlN = 0.f;
    if (beg < end) { sN = g_csr_src[beg]; xlN = g_xl2[sN * 64 + c]; }

    // self loop
    float p = lrelu(xld + xrc) * attc;
    #pragma unroll
    for (int o = 16; o > 0; o >>= 1) p += __shfl_down_sync(0xffffffffu, p, o);
    if ((c & 31) == 0) part[c >> 5] = p;
    __syncthreads();
    float w = __expf(part[0] + part[1]);
    float den = w;
    float acc = w * xld;

    for (int i = beg; i < end; i++) {
        float xls = xlN;
        if (i + 1 < end) { int s2 = g_csr_src[i + 1]; xlN = g_xl2[s2 * 64 + c]; }
        p = lrelu(xls + xrc) * attc;
        #pragma unroll
        for (int o = 16; o > 0; o >>= 1) p += __shfl_down_sync(0xffffffffu, p, o);
        __syncthreads();                 // part consumed before overwrite
        if ((c & 31) == 0) part[c >> 5] = p;
        __syncthreads();
        w = __expf(part[0] + part[1]);
        den += w;
        acc += w * xls;
    }
    out[d * 64 + c] = acc / (den + 1e-16f) + bias[c];
}

// ---------------- launch ----------------
extern "C" void kernel_launch(void* const* d_in, const int* in_sizes, int n_in,
                              void* d_out, int out_size) {
    const float* features = (const float*)d_in[0];
    const int*   edge_idx = (const int*)d_in[1];
    const float* W_ssg = (const float*)d_in[2];
    const float* b_ssg = (const float*)d_in[3];
    const float* W1l   = (const float*)d_in[4];
    const float* b1l   = (const float*)d_in[5];
    const float* W1r   = (const float*)d_in[6];
    const float* b1r   = (const float*)d_in[7];
    const float* att1  = (const float*)d_in[8];
    const float* bias1 = (const float*)d_in[9];
    const float* W2l   = (const float*)d_in[10];
    const float* b2l   = (const float*)d_in[11];
    const float* W2r   = (const float*)d_in[12];
    const float* b2r   = (const float*)d_in[13];
    const float* att2  = (const float*)d_in[14];
    const float* bias2 = (const float*)d_in[15];
    float* out = (float*)d_out;

    const int NB = (NN + 1023) / 1024;   // 98
    const int GB = (NN + 63) / 64;       // GEMM grid (64 rows/block)

    // CSR build
    k_init<<<(NN + 255) / 256, 256>>>();
    k_count<<<(EE + 255) / 256, 256>>>(edge_idx);
    k_scan1<<<NB, 1024>>>();
    k_scan2<<<1, 32>>>(NB);
    k_scan3<<<NB, 1024>>>();
    k_scatter<<<(EE + 255) / 256, 256>>>();

    // SSGConv
    k_ssg<<<NN, 64>>>(features);
    gemm_bias<0, 64, 64, 2><<<GB, 128>>>(W_ssg, b_ssg);

    // GATv2 layer 1
    gemm_bias<1, 64, 144, 4><<<GB, 144>>>(W1l, b1l);
    gemm_bias<2, 64, 144, 4><<<GB, 144>>>(W1r, b1r);
    k_gat1<<<NN, 144>>>(att1, bias1);

    // GATv2 layer 2
    gemm_bias<3, 144, 64, 2><<<GB, 128>>>(W2l, b2l);
    gemm_bias<4, 144, 64, 2><<<GB, 128>>>(W2r, b2r);
    k_gat2<<<NN, 64>>>(att2, bias2, out);
}

// round 6
// speedup vs baseline: 1.3883x; 1.0355x over previous
#include <cuda_runtime.h>

#define NN 100000
#define EE 1000000

// ---------------- static device scratch ----------------
__device__ __align__(16) int   g_dst[EE];
__device__ __align__(16) int   g_srcbuf[EE];
__device__ __align__(16) int   g_cnt[NN];
__device__ __align__(16) int   g_rowstart[NN + 1];
__device__ __align__(16) int   g_cursor[NN];
__device__ __align__(16) int   g_csr_src[EE];
__device__ __align__(16) float g_dinv[NN];
__device__ __align__(16) int   g_blocksum[128];

__device__ __align__(16) float g_h[NN * 64];
__device__ __align__(16) float g_x1[NN * 64];
__device__ __align__(16) float g_xl1[NN * 144];
__device__ __align__(16) float g_xr1[NN * 144];
__device__ __align__(16) float g_x2[NN * 144];
__device__ __align__(16) float g_xl2[NN * 64];
__device__ __align__(16) float g_xr2[NN * 64];

__device__ __forceinline__ float lrelu(float v) { return v > 0.f ? v : 0.2f * v; }

// ---------------- init ----------------
__global__ void k_init() {
    int i = blockIdx.x * blockDim.x + threadIdx.x;
    if (i < NN) g_cnt[i] = 0;
}

// ---------------- edge convert + in-degree count (edge_index is int32) ----------------
__global__ void k_count(const int* __restrict__ ei) {
    int e = blockIdx.x * blockDim.x + threadIdx.x;
    if (e >= EE) return;
    int s = ei[e];
    int d = ei[EE + e];
    g_srcbuf[e] = s;
    g_dst[e] = d;
    atomicAdd(&g_cnt[d], 1);
}

// ---------------- scan ----------------
__global__ void k_scan1() {
    __shared__ int sm[1024];
    int i = blockIdx.x * 1024 + threadIdx.x;
    int v = (i < NN) ? g_cnt[i] : 0;
    if (i < NN) g_dinv[i] = rsqrtf((float)(v + 1));
    sm[threadIdx.x] = v;
    __syncthreads();
    for (int off = 1; off < 1024; off <<= 1) {
        int t = 0;
        if (threadIdx.x >= off) t = sm[threadIdx.x - off];
        __syncthreads();
        sm[threadIdx.x] += t;
        __syncthreads();
    }
    if (i < NN) g_rowstart[i] = sm[threadIdx.x] - v;
    if (threadIdx.x == 1023) g_blocksum[blockIdx.x] = sm[1023];
}
__global__ void k_scan2(int nb) {   // parallel 128-thread ladder
    __shared__ int sm[128];
    int t = threadIdx.x;
    int v = (t < nb) ? g_blocksum[t] : 0;
    sm[t] = v;
    __syncthreads();
    for (int off = 1; off < 128; off <<= 1) {
        int u = 0;
        if (t >= off) u = sm[t - off];
        __syncthreads();
        sm[t] += u;
        __syncthreads();
    }
    if (t < nb) g_blocksum[t] = sm[t] - v;   // exclusive
}
__global__ void k_scan3() {
    int i = blockIdx.x * 1024 + threadIdx.x;
    if (i < NN) {
        int v = g_rowstart[i] + g_blocksum[blockIdx.x];
        g_rowstart[i] = v;
        g_cursor[i]   = v;
    }
    if (i == 0) g_rowstart[NN] = EE;
}

// ---------------- scatter ----------------
__global__ void k_scatter() {
    int e = blockIdx.x * blockDim.x + threadIdx.x;
    if (e >= EE) return;
    int d = g_dst[e];
    int pos = atomicAdd(&g_cursor[d], 1);
    g_csr_src[pos] = g_srcbuf[e];
}

// ---------------- SSGConv: warp per dst, 2 channels/thread, batch 8 ----------------
__global__ void k_ssg(const float* __restrict__ x) {
    int wid = threadIdx.x >> 5, lane = threadIdx.x & 31;
    int d = blockIdx.x * 8 + wid;
    if (d >= NN) return;
    float dd = g_dinv[d];
    float x0 = x[d * 64 + lane];
    float x1 = x[d * 64 + lane + 32];
    float acc0 = 0.f, acc1 = 0.f;
    int beg = g_rowstart[d], end = g_rowstart[d + 1];
    for (int i = beg; i < end; i += 8) {
        int n = end - i; if (n > 8) n = 8;
        float v0[8], v1[8], dv[8];
        #pragma unroll
        for (int k = 0; k < 8; k++) if (k < n) {
            int s = g_csr_src[i + k];
            v0[k] = x[s * 64 + lane];
            v1[k] = x[s * 64 + lane + 32];
            dv[k] = g_dinv[s];
        }
        #pragma unroll
        for (int k = 0; k < 8; k++) if (k < n) {
            acc0 += v0[k] * dv[k];
            acc1 += v1[k] * dv[k];
        }
    }
    // h = 0.5*x + 0.5*(x*dd*dd + dd*sum)
    g_h[d * 64 + lane]      = 0.5f * x0 + 0.5f * (x0 * dd * dd + dd * acc0);
    g_h[d * 64 + lane + 32] = 0.5f * x1 + 0.5f * (x1 * dd * dd + dd * acc1);
}

// ---------------- skinny GEMM: 128 rows per block (8 chunks reuse smem W) ----------------
template <int SEL, int K, int M, int CPT>
__global__ void gemm_bias(const float* __restrict__ W, const float* __restrict__ b) {
    const float* X;
    float* Y;
    if constexpr (SEL == 0)      { X = g_h;  Y = g_x1;  }
    else if constexpr (SEL == 1) { X = g_x1; Y = g_xl1; }
    else if constexpr (SEL == 2) { X = g_x1; Y = g_xr1; }
    else if constexpr (SEL == 3) { X = g_x2; Y = g_xl2; }
    else                         { X = g_x2; Y = g_xr2; }

    constexpr int ROWS = 16, RPT = 4, CHUNK = 8;
    constexpr int TC = M / CPT, TR = ROWS / RPT, NT = TC * TR;
    constexpr int K4 = K / 4;
    __shared__ float Ws[K * M];
    __shared__ float Xs[ROWS * K];

    for (int i = threadIdx.x; i < K * M; i += NT) Ws[i] = W[i];

    int tc = threadIdx.x % TC;
    int tr = threadIdx.x / TC;
    float bv[CPT];
    #pragma unroll
    for (int cc = 0; cc < CPT; cc++) bv[cc] = b[tc + cc * TC];

    #pragma unroll
    for (int ch = 0; ch < CHUNK; ch++) {
        int row0 = (blockIdx.x * CHUNK + ch) * ROWS;
        if (row0 >= NN) break;
        __syncthreads();
        for (int i4 = threadIdx.x; i4 < ROWS * K4; i4 += NT) {
            int r = row0 + i4 / K4;
            int c4 = i4 % K4;
            if (r >= NN) r = NN - 1;
            float4 v = *(const float4*)&X[r * K + c4 * 4];
            *(float4*)&Xs[(i4 / K4) * K + c4 * 4] = v;
        }
        __syncthreads();
        float acc[RPT][CPT];
        #pragma unroll
        for (int rr = 0; rr < RPT; rr++)
            #pragma unroll
            for (int cc = 0; cc < CPT; cc++) acc[rr][cc] = bv[cc];
        #pragma unroll 4
        for (int k = 0; k < K; k++) {
            float xv[RPT], wv[CPT];
            #pragma unroll
            for (int rr = 0; rr < RPT; rr++) xv[rr] = Xs[(tr * RPT + rr) * K + k];
            #pragma unroll
            for (int cc = 0; cc < CPT; cc++) wv[cc] = Ws[k * M + tc + cc * TC];
            #pragma unroll
            for (int rr = 0; rr < RPT; rr++)
                #pragma unroll
                for (int cc = 0; cc < CPT; cc++) acc[rr][cc] += xv[rr] * wv[cc];
        }
        #pragma unroll
        for (int rr = 0; rr < RPT; rr++) {
            int r = row0 + tr * RPT + rr;
            if (r < NN) {
                #pragma unroll
                for (int cc = 0; cc < CPT; cc++) Y[r * M + tc + cc * TC] = acc[rr][cc];
            }
        }
    }
}

// ---------------- fused GATv2 layer 1: batched (8 edges / 3 syncs) ----------------
__global__ void k_gat1(const float* __restrict__ att, const float* __restrict__ bias) {
    int d = blockIdx.x, c = threadIdx.x;   // 144 threads
    int h = c / 12;
    __shared__ float prod[8][144];
    __shared__ float wsh[8][12];
    __shared__ float dshf[12];

    float attc = __ldg(&att[c]);
    float xrc  = g_xr1[d * 144 + c];
    float xld  = g_xl1[d * 144 + c];

    int beg = g_rowstart[d], end = g_rowstart[d + 1];

    // self loop (batch of 1)
    prod[0][c] = lrelu(xld + xrc) * attc;
    __syncthreads();
    if (c < 12) {
        float s = 0.f;
        #pragma unroll
        for (int j = 0; j < 12; j++) s += prod[0][c * 12 + j];
        wsh[0][c] = __expf(s);
    }
    __syncthreads();
    float acc = wsh[0][h] * xld;
    float den = (c < 12) ? wsh[0][c] : 0.f;

    for (int i = beg; i < end; i += 8) {
        int n = end - i; if (n > 8) n = 8;
        float xls[8];
        #pragma unroll
        for (int k = 0; k < 8; k++) if (k < n) {
            int s = g_csr_src[i + k];
            xls[k] = g_xl1[s * 144 + c];
        }
        __syncthreads();   // previous batch's wsh fully consumed
        #pragma unroll
        for (int k = 0; k < 8; k++) if (k < n)
            prod[k][c] = lrelu(xls[k] + xrc) * attc;
        __syncthreads();
        if (c < 12 * n) {
            int k = c / 12, hh = c - k * 12;
            float s = 0.f;
            #pragma unroll
            for (int j = 0; j < 12; j++) s += prod[k][hh * 12 + j];
            wsh[k][hh] = __expf(s);
        }
        __syncthreads();
        #pragma unroll
        for (int k = 0; k < 8; k++) if (k < n)
            acc += wsh[k][h] * xls[k];
        if (c < 12) {
            #pragma unroll
            for (int k = 0; k < 8; k++) if (k < n) den += wsh[k][c];
        }
    }
    if (c < 12) dshf[c] = den;
    __syncthreads();
    g_x2[d * 144 + c] = acc / (dshf[h] + 1e-16f) + bias[c];
}

// ---------------- fused GATv2 layer 2: warp per dst, no syncs, batch 8 ----------------
__global__ void k_gat2(const float* __restrict__ att, const float* __restrict__ bias,
                       float* __restrict__ out) {
    int wid = threadIdx.x >> 5, lane = threadIdx.x & 31;
    int d = blockIdx.x * 8 + wid;
    if (d >= NN) return;

    float a0 = __ldg(&att[lane]);
    float a1 = __ldg(&att[lane + 32]);
    float r0 = g_xr2[d * 64 + lane];
    float r1 = g_xr2[d * 64 + lane + 32];
    float l0 = g_xl2[d * 64 + lane];
    float l1 = g_xl2[d * 64 + lane + 32];

    // self loop
    float p = lrelu(l0 + r0) * a0 + lrelu(l1 + r1) * a1;
    #pragma unroll
    for (int o = 16; o > 0; o >>= 1) p += __shfl_xor_sync(0xffffffffu, p, o);
    float w = __expf(p);
    float den = w;
    float acc0 = w * l0, acc1 = w * l1;

    int beg = g_rowstart[d], end = g_rowstart[d + 1];
    for (int i = beg; i < end; i += 8) {
        int n = end - i; if (n > 8) n = 8;
        float x0[8], x1[8];
        #pragma unroll
        for (int k = 0; k < 8; k++) if (k < n) {
            int s = g_csr_src[i + k];
            x0[k] = g_xl2[s * 64 + lane];
            x1[k] = g_xl2[s * 64 + lane + 32];
        }
        #pragma unroll
        for (int k = 0; k < 8; k++) if (k < n) {
            float q = lrelu(x0[k] + r0) * a0 + lrelu(x1[k] + r1) * a1;
            #pragma unroll
            for (int o = 16; o > 0; o >>= 1) q += __shfl_xor_sync(0xffffffffu, q, o);
            float ww = __expf(q);
            den += ww;
            acc0 += ww * x0[k];
            acc1 += ww * x1[k];
        }
    }
    float inv = 1.f / (den + 1e-16f);
    out[d * 64 + lane]      = acc0 * inv + __ldg(&bias[lane]);
    out[d * 64 + lane + 32] = acc1 * inv + __ldg(&bias[lane + 32]);
}

// ---------------- launch ----------------
extern "C" void kernel_launch(void* const* d_in, const int* in_sizes, int n_in,
                              void* d_out, int out_size) {
    const float* features = (const float*)d_in[0];
    const int*   edge_idx = (const int*)d_in[1];
    const float* W_ssg = (const float*)d_in[2];
    const float* b_ssg = (const float*)d_in[3];
    const float* W1l   = (const float*)d_in[4];
    const float* b1l   = (const float*)d_in[5];
    const float* W1r   = (const float*)d_in[6];
    const float* b1r   = (const float*)d_in[7];
    const float* att1  = (const float*)d_in[8];
    const float* bias1 = (const float*)d_in[9];
    const float* W2l   = (const float*)d_in[10];
    const float* b2l   = (const float*)d_in[11];
    const float* W2r   = (const float*)d_in[12];
    const float* b2r   = (const float*)d_in[13];
    const float* att2  = (const float*)d_in[14];
    const float* bias2 = (const float*)d_in[15];
    float* out = (float*)d_out;

    const int NB = (NN + 1023) / 1024;   // 98
    const int GB = (NN + 127) / 128;     // GEMM grid (128 rows/block)
    const int WB = (NN + 7) / 8;         // warp-per-dst grids

    // CSR build
    k_init<<<(NN + 255) / 256, 256>>>();
    k_count<<<(EE + 255) / 256, 256>>>(edge_idx);
    k_scan1<<<NB, 1024>>>();
    k_scan2<<<1, 128>>>(NB);
    k_scan3<<<NB, 1024>>>();
    k_scatter<<<(EE + 255) / 256, 256>>>();

    // SSGConv
    k_ssg<<<WB, 256>>>(features);
    gemm_bias<0, 64, 64, 2><<<GB, 128>>>(W_ssg, b_ssg);

    // GATv2 layer 1
    gemm_bias<1, 64, 144, 4><<<GB, 144>>>(W1l, b1l);
    gemm_bias<2, 64, 144, 4><<<GB, 144>>>(W1r, b1r);
    k_gat1<<<NN, 144>>>(att1, bias1);

    // GATv2 layer 2
    gemm_bias<3, 144, 64, 2><<<GB, 128>>>(W2l, b2l);
    gemm_bias<4, 144, 64, 2><<<GB, 128>>>(W2r, b2r);
    k_gat2<<<WB, 256>>>(att2, bias2, out);
}